// round 3
// baseline (speedup 1.0000x reference)
#include <cuda_runtime.h>
#include <math.h>

// ---------------- problem constants ----------------
#define Lc   4
#define Bc   64
#define Nc   197
#define Cc   768
#define NHc  12
#define HDc  64
#define HFc  2048
#define BNc  (Bc*Nc)          // 12608
#define SCALEc 0.125f         // 64^-0.5
#define EPSc   1e-6f

// ---------------- scratch (static device globals; no allocation) ----------------
__device__ float g_y  [BNc*Cc];        // LN output
__device__ float g_qkv[BNc*3*Cc];      // fused qkv GEMM output
__device__ float g_q  [BNc*Cc];        // [B,NH,N,HD]
__device__ float g_k  [BNc*Cc];
__device__ float g_v  [BNc*Cc];
__device__ float g_s  [Bc*NHc*Nc*Nc];  // attention scores
__device__ float g_ao [BNc*Cc];        // attention out, [BN,C]
__device__ float g_g1 [BNc*HFc];       // gate -> silu*x -> LN (reused in place)
__device__ float g_g2 [BNc*HFc];       // value branch

// ---------------- elementwise helpers ----------------
__global__ void copy_kernel(float* __restrict__ dst, const float* __restrict__ src, int n) {
    int i = blockIdx.x * blockDim.x + threadIdx.x;
    if (i < n) dst[i] = src[i];
}

// in-place: gate[i] = silu(gate[i]) * xv[i]
__global__ void silu_mul_kernel(float* __restrict__ gate,
                                const float* __restrict__ xv, int n) {
    int i = blockIdx.x * blockDim.x + threadIdx.x;
    if (i < n) {
        float z = gate[i];
        float sg = z / (1.f + __expf(-z));
        gate[i] = sg * xv[i];
    }
}

// fused: qkv [BN,3C] -> q/k/v [B,NH,N,HD] with biases and interleaved RoPE
// (RoPE applied to q,k for tokens >= 1; CLS token passes through).
// One thread per (b, head, token, pair); handles 2 elems each of q, k, v.
__global__ void qkv_rope_kernel(const float* __restrict__ qkv,
                                const float* __restrict__ qb,
                                const float* __restrict__ vb,
                                const float* __restrict__ rope,
                                float* __restrict__ q, float* __restrict__ k,
                                float* __restrict__ v) {
    const int total = Bc * NHc * Nc * (HDc / 2);
    int idx = blockIdx.x * blockDim.x + threadIdx.x;
    if (idx >= total) return;
    int p   = idx & 31;                  // pair 0..31
    int tkn = (idx >> 5) % Nc;
    int bh  = idx / (32 * Nc);
    int b = bh / NHc, hh = bh - b * NHc;
    int d0 = p * 2;
    int cidx = hh * HDc + d0;            // channel within C

    const float* src = qkv + ((size_t)(b * Nc + tkn)) * (3 * Cc);
    float q0 = src[cidx]            + qb[cidx];
    float q1 = src[cidx + 1]        + qb[cidx + 1];
    float k0 = src[Cc + cidx];
    float k1 = src[Cc + cidx + 1];
    float v0 = src[2 * Cc + cidx]     + vb[cidx];
    float v1 = src[2 * Cc + cidx + 1] + vb[cidx + 1];

    if (tkn > 0) {
        const float* rr = rope + (size_t)(tkn - 1) * (2 * HDc);  // [sin(64) | cos(64)]
        float s0 = rr[d0], s1 = rr[d0 + 1];
        float c0 = rr[HDc + d0], c1 = rr[HDc + d0 + 1];
        float nq0 = q0 * c0 - q1 * s0;
        float nq1 = q1 * c1 + q0 * s1;
        float nk0 = k0 * c0 - k1 * s0;
        float nk1 = k1 * c1 + k0 * s1;
        q0 = nq0; q1 = nq1; k0 = nk0; k1 = nk1;
    }
    size_t dst = ((size_t)bh * Nc + tkn) * HDc + d0;
    q[dst] = q0; q[dst + 1] = q1;
    k[dst] = k0; k[dst + 1] = k1;
    v[dst] = v0; v[dst + 1] = v1;
}

// ---------------- LayerNorm (block per row; register-resident, in-place safe) ----------------
template <int W>
__global__ void ln_kernel(const float* __restrict__ x, const float* __restrict__ g,
                          const float* __restrict__ b, float* __restrict__ y) {
    constexpr int TPB = 256;
    constexpr int E = W / TPB;
    int row = blockIdx.x;
    const float* xr = x + (size_t)row * W;
    float v[E];
    float s = 0.f, s2 = 0.f;
#pragma unroll
    for (int e = 0; e < E; e++) {
        v[e] = xr[threadIdx.x + e * TPB];
        s += v[e];
        s2 += v[e] * v[e];
    }
    __shared__ float sh1[8], sh2[8];
#pragma unroll
    for (int o = 16; o; o >>= 1) {
        s  += __shfl_xor_sync(0xFFFFFFFFu, s, o);
        s2 += __shfl_xor_sync(0xFFFFFFFFu, s2, o);
    }
    int w = threadIdx.x >> 5;
    if ((threadIdx.x & 31) == 0) { sh1[w] = s; sh2[w] = s2; }
    __syncthreads();
    if (threadIdx.x < 32) {
        s  = (threadIdx.x < 8) ? sh1[threadIdx.x] : 0.f;
        s2 = (threadIdx.x < 8) ? sh2[threadIdx.x] : 0.f;
#pragma unroll
        for (int o = 4; o; o >>= 1) {
            s  += __shfl_xor_sync(0xFFFFFFFFu, s, o);
            s2 += __shfl_xor_sync(0xFFFFFFFFu, s2, o);
        }
        if (threadIdx.x == 0) { sh1[0] = s; sh2[0] = s2; }
    }
    __syncthreads();
    const float inv = 1.0f / (float)W;
    float m   = sh1[0] * inv;
    float var = sh2[0] * inv - m * m;
    float rs  = rsqrtf(var + EPSc);
    float* yr = y + (size_t)row * W;
#pragma unroll
    for (int e = 0; e < E; e++) {
        int cidx = threadIdx.x + e * TPB;
        yr[cidx] = (v[e] - m) * rs * g[cidx] + b[cidx];
    }
}

// ---------------- SGEMM: C[M,Nn] = A[M,K] @ W[Nn,K]^T (+bias) (+accumulate into C) -------------
// BM=64, BN=128, BK=16, 256 threads, 4x8 per-thread microtile.
// Requires M%64==0, Nn%128==0, K%16==0 (all satisfied).
template <bool ACCUM>
__global__ __launch_bounds__(256) void sgemm_tn(const float* __restrict__ A,
                                                const float* __restrict__ W,
                                                const float* __restrict__ bias,
                                                float* __restrict__ C,
                                                int M, int Nn, int K) {
    __shared__ float As[16][64];
    __shared__ float Ws[16][128];
    int t = threadIdx.x;
    int tx = t & 15, ty = t >> 4;
    const float* Ab = A + (size_t)(blockIdx.y * 64) * K;
    const float* Wb = W + (size_t)(blockIdx.x * 128) * K;

    float acc[4][8];
#pragma unroll
    for (int i = 0; i < 4; i++)
#pragma unroll
        for (int j = 0; j < 8; j++) acc[i][j] = 0.f;

    int lr = t >> 2;           // 0..63
    int lc = (t & 3) * 4;      // 0,4,8,12

    for (int k0 = 0; k0 < K; k0 += 16) {
        float4 av = *(const float4*)(Ab + (size_t)lr * K + k0 + lc);
        As[lc + 0][lr] = av.x; As[lc + 1][lr] = av.y;
        As[lc + 2][lr] = av.z; As[lc + 3][lr] = av.w;
        float4 w0 = *(const float4*)(Wb + (size_t)lr * K + k0 + lc);
        float4 w1 = *(const float4*)(Wb + (size_t)(lr + 64) * K + k0 + lc);
        Ws[lc + 0][lr]      = w0.x; Ws[lc + 1][lr]      = w0.y;
        Ws[lc + 2][lr]      = w0.z; Ws[lc + 3][lr]      = w0.w;
        Ws[lc + 0][lr + 64] = w1.x; Ws[lc + 1][lr + 64] = w1.y;
        Ws[lc + 2][lr + 64] = w1.z; Ws[lc + 3][lr + 64] = w1.w;
        __syncthreads();
#pragma unroll
        for (int kk = 0; kk < 16; kk++) {
            float a[4], w[8];
#pragma unroll
            for (int i = 0; i < 4; i++) a[i] = As[kk][ty * 4 + i];
#pragma unroll
            for (int j = 0; j < 8; j++) w[j] = Ws[kk][tx * 8 + j];
#pragma unroll
            for (int i = 0; i < 4; i++)
#pragma unroll
                for (int j = 0; j < 8; j++) acc[i][j] += a[i] * w[j];
        }
        __syncthreads();
    }

    int row0 = blockIdx.y * 64 + ty * 4;
    int col0 = blockIdx.x * 128 + tx * 8;
    float bv[8];
#pragma unroll
    for (int j = 0; j < 8; j++) bv[j] = bias ? bias[col0 + j] : 0.f;
#pragma unroll
    for (int i = 0; i < 4; i++) {
        float* Cr = C + (size_t)(row0 + i) * Nn + col0;
#pragma unroll
        for (int j = 0; j < 8; j++) {
            float val = acc[i][j] + bv[j];
            if (ACCUM) Cr[j] += val; else Cr[j] = val;
        }
    }
}

// ---------------- attention: scores = SCALE * q @ k^T, batched over B*NH ----------------
__global__ __launch_bounds__(256) void attn_scores(const float* __restrict__ q,
                                                   const float* __restrict__ k,
                                                   float* __restrict__ s) {
    int bh = blockIdx.z;
    __shared__ float Qs[64][33];   // [kk][row]
    __shared__ float Ks[64][33];
    int t = threadIdx.x;
    int r = t >> 3;               // 0..31
    int c = (t & 7) * 8;          // 0..56
    const float* qb = q + (size_t)bh * Nc * HDc;
    const float* kb = k + (size_t)bh * Nc * HDc;
    int qi = blockIdx.y * 32 + r;
    int ki = blockIdx.x * 32 + r;
#pragma unroll
    for (int u = 0; u < 8; u++) {
        Qs[c + u][r] = (qi < Nc) ? qb[(size_t)qi * HDc + c + u] : 0.f;
        Ks[c + u][r] = (ki < Nc) ? kb[(size_t)ki * HDc + c + u] : 0.f;
    }
    __syncthreads();
    int tx = t & 15, ty = t >> 4;
    float acc00 = 0.f, acc01 = 0.f, acc10 = 0.f, acc11 = 0.f;
#pragma unroll 8
    for (int kk = 0; kk < 64; kk++) {
        float a0 = Qs[kk][ty * 2], a1 = Qs[kk][ty * 2 + 1];
        float b0 = Ks[kk][tx * 2], b1 = Ks[kk][tx * 2 + 1];
        acc00 += a0 * b0; acc01 += a0 * b1;
        acc10 += a1 * b0; acc11 += a1 * b1;
    }
    float accs[2][2] = {{acc00, acc01}, {acc10, acc11}};
#pragma unroll
    for (int ii = 0; ii < 2; ii++)
#pragma unroll
        for (int jj = 0; jj < 2; jj++) {
            int i = blockIdx.y * 32 + ty * 2 + ii;
            int j = blockIdx.x * 32 + tx * 2 + jj;
            if (i < Nc && j < Nc)
                s[((size_t)bh * Nc + i) * Nc + j] = accs[ii][jj] * SCALEc;
        }
}

// ---------------- softmax: one warp per row of length 197 ----------------
__global__ void softmax_kernel(float* __restrict__ s) {
    const int rows = Bc * NHc * Nc;
    int row = blockIdx.x * 4 + (threadIdx.x >> 5);
    if (row >= rows) return;
    int lane = threadIdx.x & 31;
    float* p = s + (size_t)row * Nc;
    float vals[7];
    float mx = -3.0e38f;
#pragma unroll
    for (int i = 0; i < 7; i++) {
        int j = lane + i * 32;
        vals[i] = (j < Nc) ? p[j] : -3.0e38f;
        mx = fmaxf(mx, vals[i]);
    }
#pragma unroll
    for (int o = 16; o; o >>= 1) mx = fmaxf(mx, __shfl_xor_sync(0xFFFFFFFFu, mx, o));
    float sum = 0.f;
#pragma unroll
    for (int i = 0; i < 7; i++) {
        int j = lane + i * 32;
        float e = (j < Nc) ? __expf(vals[i] - mx) : 0.f;
        vals[i] = e;
        sum += e;
    }
#pragma unroll
    for (int o = 16; o; o >>= 1) sum += __shfl_xor_sync(0xFFFFFFFFu, sum, o);
    float inv = 1.f / sum;
#pragma unroll
    for (int i = 0; i < 7; i++) {
        int j = lane + i * 32;
        if (j < Nc) p[j] = vals[i] * inv;
    }
}

// ---------------- attention: O = S @ V, output written to [BN, C] layout ----------------
__global__ __launch_bounds__(256) void attn_pv(const float* __restrict__ s,
                                               const float* __restrict__ v,
                                               float* __restrict__ o) {
    int bh = blockIdx.y;
    int b = bh / NHc, h = bh - b * NHc;
    __shared__ float Ss[32][33];   // [i][j]
    __shared__ float Vs[32][65];   // [j][d]
    int t = threadIdx.x;
    int tx = t & 15, ty = t >> 4;
    float acc[2][4] = {};
    for (int j0 = 0; j0 < Nc; j0 += 32) {
        int r = t >> 3;            // 0..31
        int c4 = (t & 7) * 4;
        int gi = blockIdx.x * 32 + r;
#pragma unroll
        for (int u = 0; u < 4; u++) {
            int gj = j0 + c4 + u;
            Ss[r][c4 + u] = (gi < Nc && gj < Nc)
                          ? s[((size_t)bh * Nc + gi) * Nc + gj] : 0.f;
        }
        int c8 = (t & 7) * 8;
        int gj = j0 + r;
#pragma unroll
        for (int u = 0; u < 8; u++)
            Vs[r][c8 + u] = (gj < Nc) ? v[((size_t)bh * Nc + gj) * HDc + c8 + u] : 0.f;
        __syncthreads();
#pragma unroll 8
        for (int kk = 0; kk < 32; kk++) {
            float a0 = Ss[ty * 2][kk], a1 = Ss[ty * 2 + 1][kk];
#pragma unroll
            for (int jj = 0; jj < 4; jj++) {
                float w = Vs[kk][tx * 4 + jj];
                acc[0][jj] += a0 * w;
                acc[1][jj] += a1 * w;
            }
        }
        __syncthreads();
    }
#pragma unroll
    for (int ii = 0; ii < 2; ii++) {
        int i = blockIdx.x * 32 + ty * 2 + ii;
        if (i < Nc) {
#pragma unroll
            for (int jj = 0; jj < 4; jj++)
                o[((size_t)(b * Nc + i)) * Cc + h * HDc + tx * 4 + jj] = acc[ii][jj];
        }
    }
}

// ---------------- host orchestration ----------------
extern "C" void kernel_launch(void* const* d_in, const int* in_sizes, int n_in,
                              void* d_out, int out_size) {
    const float* x    = (const float*)d_in[0];
    const float* rope = (const float*)d_in[1];
    const float* qkvw = (const float*)d_in[2];
    const float* qb   = (const float*)d_in[3];
    const float* vb   = (const float*)d_in[4];
    const float* pw   = (const float*)d_in[5];
    const float* pb   = (const float*)d_in[6];
    const float* n1g  = (const float*)d_in[7];
    const float* n1b  = (const float*)d_in[8];
    const float* n2g  = (const float*)d_in[9];
    const float* n2b  = (const float*)d_in[10];
    const float* w1g  = (const float*)d_in[11];
    const float* b1g  = (const float*)d_in[12];
    const float* w1x  = (const float*)d_in[13];
    const float* b1x  = (const float*)d_in[14];
    const float* nmg  = (const float*)d_in[15];
    const float* nmb  = (const float*)d_in[16];
    const float* w2   = (const float*)d_in[17];
    const float* b2   = (const float*)d_in[18];
    float* h = (float*)d_out;

    float *yb, *qkvb, *qbuf, *kbuf, *vbuf, *sb, *aob, *g1b, *g2b;
    cudaGetSymbolAddress((void**)&yb,   g_y);
    cudaGetSymbolAddress((void**)&qkvb, g_qkv);
    cudaGetSymbolAddress((void**)&qbuf, g_q);
    cudaGetSymbolAddress((void**)&kbuf, g_k);
    cudaGetSymbolAddress((void**)&vbuf, g_v);
    cudaGetSymbolAddress((void**)&sb,   g_s);
    cudaGetSymbolAddress((void**)&aob,  g_ao);
    cudaGetSymbolAddress((void**)&g1b,  g_g1);
    cudaGetSymbolAddress((void**)&g2b,  g_g2);

    const int nHC = BNc * Cc;
    // h = x
    copy_kernel<<<(nHC + 255) / 256, 256>>>(h, x, nHC);

    for (int l = 0; l < Lc; l++) {
        const float* qkvw_l = qkvw + (size_t)l * 3 * Cc * Cc;
        const float* qb_l   = qb   + (size_t)l * Cc;
        const float* vb_l   = vb   + (size_t)l * Cc;
        const float* pw_l   = pw   + (size_t)l * Cc * Cc;
        const float* pb_l   = pb   + (size_t)l * Cc;
        const float* n1g_l  = n1g  + (size_t)l * Cc;
        const float* n1b_l  = n1b  + (size_t)l * Cc;
        const float* n2g_l  = n2g  + (size_t)l * Cc;
        const float* n2b_l  = n2b  + (size_t)l * Cc;
        const float* w1g_l  = w1g  + (size_t)l * HFc * Cc;
        const float* b1g_l  = b1g  + (size_t)l * HFc;
        const float* w1x_l  = w1x  + (size_t)l * HFc * Cc;
        const float* b1x_l  = b1x  + (size_t)l * HFc;
        const float* nmg_l  = nmg  + (size_t)l * HFc;
        const float* nmb_l  = nmb  + (size_t)l * HFc;
        const float* w2_l   = w2   + (size_t)l * Cc * HFc;
        const float* b2_l   = b2   + (size_t)l * Cc;

        // --- attention ---
        ln_kernel<Cc><<<BNc, 256>>>(h, n1g_l, n1b_l, yb);
        sgemm_tn<false><<<dim3(3 * Cc / 128, BNc / 64), 256>>>(
            yb, qkvw_l, nullptr, qkvb, BNc, 3 * Cc, Cc);
        {
            int n = Bc * NHc * Nc * (HDc / 2);
            qkv_rope_kernel<<<(n + 255) / 256, 256>>>(qkvb, qb_l, vb_l, rope,
                                                      qbuf, kbuf, vbuf);
        }
        attn_scores<<<dim3((Nc + 31) / 32, (Nc + 31) / 32, Bc * NHc), 256>>>(qbuf, kbuf, sb);
        {
            int rows = Bc * NHc * Nc;
            softmax_kernel<<<(rows + 3) / 4, 128>>>(sb);
        }
        attn_pv<<<dim3((Nc + 31) / 32, Bc * NHc), 256>>>(sb, vbuf, aob);
        // h += attn_out @ proj^T + proj_b
        sgemm_tn<true><<<dim3(Cc / 128, BNc / 64), 256>>>(
            aob, pw_l, pb_l, h, BNc, Cc, Cc);

        // --- SwiGLU MLP with inner LN ---
        ln_kernel<Cc><<<BNc, 256>>>(h, n2g_l, n2b_l, yb);
        sgemm_tn<false><<<dim3(HFc / 128, BNc / 64), 256>>>(
            yb, w1g_l, b1g_l, g1b, BNc, HFc, Cc);
        sgemm_tn<false><<<dim3(HFc / 128, BNc / 64), 256>>>(
            yb, w1x_l, b1x_l, g2b, BNc, HFc, Cc);
        {
            int n = BNc * HFc;
            silu_mul_kernel<<<(n + 255) / 256, 256>>>(g1b, g2b, n);
        }
        ln_kernel<HFc><<<BNc, 256>>>(g1b, nmg_l, nmb_l, g1b);
        // h += u @ w2^T + b2
        sgemm_tn<true><<<dim3(Cc / 128, BNc / 64), 256>>>(
            g1b, w2_l, b2_l, h, BNc, Cc, HFc);
    }
}

// round 4
// speedup vs baseline: 3.3510x; 3.3510x over previous
#include <cuda_runtime.h>
#include <math.h>
#include <stdint.h>

// ---------------- problem constants ----------------
#define Lc   4
#define Bc   64
#define Nc   197
#define Cc   768
#define NHc  12
#define HDc  64
#define HFc  2048
#define BNc  (Bc*Nc)          // 12608 = 197*64
#define SCALEc 0.125f         // 64^-0.5
#define EPSc   1e-6f

// ---------------- scratch (static device globals; no allocation) ----------------
__device__ float g_y  [BNc*Cc];        // LN output
__device__ float g_qkv[BNc*3*Cc];      // fused qkv GEMM output
__device__ float g_q  [BNc*Cc];        // [B,NH,N,HD]
__device__ float g_k  [BNc*Cc];
__device__ float g_v  [BNc*Cc];
__device__ float g_s  [Bc*NHc*Nc*Nc];  // attention scores
__device__ float g_ao [BNc*Cc];        // attention out, [BN,C]
__device__ float g_g1 [BNc*HFc];       // gate -> silu*x -> LN (in place)
__device__ float g_g2 [BNc*HFc];       // value branch

// ---------------- small device helpers ----------------
__device__ __forceinline__ uint32_t smem_u32(const void* p) {
    return (uint32_t)__cvta_generic_to_shared(p);
}
__device__ __forceinline__ uint32_t f2tf32(float x) {
    uint32_t r;
    asm("cvt.rna.tf32.f32 %0, %1;" : "=r"(r) : "f"(x));
    return r;
}
__device__ __forceinline__ void mma_tf32(float* c, const uint32_t* a, const uint32_t* b) {
    asm volatile(
        "mma.sync.aligned.m16n8k8.row.col.f32.tf32.tf32.f32 "
        "{%0,%1,%2,%3},{%4,%5,%6,%7},{%8,%9},{%0,%1,%2,%3};"
        : "+f"(c[0]), "+f"(c[1]), "+f"(c[2]), "+f"(c[3])
        : "r"(a[0]), "r"(a[1]), "r"(a[2]), "r"(a[3]), "r"(b[0]), "r"(b[1]));
}
__device__ __forceinline__ void cp16(uint32_t saddr, const void* gaddr) {
    asm volatile("cp.async.cg.shared.global [%0], [%1], 16;" :: "r"(saddr), "l"(gaddr));
}

// ---------------- elementwise helpers ----------------
__global__ void copy_kernel(float* __restrict__ dst, const float* __restrict__ src, int n) {
    int i = blockIdx.x * blockDim.x + threadIdx.x;
    if (i < n) dst[i] = src[i];
}

// in-place: gate[i] = silu(gate[i]) * xv[i]
__global__ void silu_mul_kernel(float* __restrict__ gate,
                                const float* __restrict__ xv, int n) {
    int i = blockIdx.x * blockDim.x + threadIdx.x;
    if (i < n) {
        float z = gate[i];
        float sg = z / (1.f + __expf(-z));
        gate[i] = sg * xv[i];
    }
}

// fused: qkv [BN,3C] -> q/k/v [B,NH,N,HD] with biases and interleaved RoPE
__global__ void qkv_rope_kernel(const float* __restrict__ qkv,
                                const float* __restrict__ qb,
                                const float* __restrict__ vb,
                                const float* __restrict__ rope,
                                float* __restrict__ q, float* __restrict__ k,
                                float* __restrict__ v) {
    const int total = Bc * NHc * Nc * (HDc / 2);
    int idx = blockIdx.x * blockDim.x + threadIdx.x;
    if (idx >= total) return;
    int p   = idx & 31;                  // pair 0..31
    int tkn = (idx >> 5) % Nc;
    int bh  = idx / (32 * Nc);
    int b = bh / NHc, hh = bh - b * NHc;
    int d0 = p * 2;
    int cidx = hh * HDc + d0;

    const float* src = qkv + ((size_t)(b * Nc + tkn)) * (3 * Cc);
    float q0 = src[cidx]            + qb[cidx];
    float q1 = src[cidx + 1]        + qb[cidx + 1];
    float k0 = src[Cc + cidx];
    float k1 = src[Cc + cidx + 1];
    float v0 = src[2 * Cc + cidx]     + vb[cidx];
    float v1 = src[2 * Cc + cidx + 1] + vb[cidx + 1];

    if (tkn > 0) {
        const float* rr = rope + (size_t)(tkn - 1) * (2 * HDc);  // [sin(64)|cos(64)]
        float s0 = rr[d0], s1 = rr[d0 + 1];
        float c0 = rr[HDc + d0], c1 = rr[HDc + d0 + 1];
        float nq0 = q0 * c0 - q1 * s0;
        float nq1 = q1 * c1 + q0 * s1;
        float nk0 = k0 * c0 - k1 * s0;
        float nk1 = k1 * c1 + k0 * s1;
        q0 = nq0; q1 = nq1; k0 = nk0; k1 = nk1;
    }
    size_t dst = ((size_t)bh * Nc + tkn) * HDc + d0;
    q[dst] = q0; q[dst + 1] = q1;
    k[dst] = k0; k[dst + 1] = k1;
    v[dst] = v0; v[dst + 1] = v1;
}

// ---------------- LayerNorm ----------------
template <int W>
__global__ void ln_kernel(const float* __restrict__ x, const float* __restrict__ g,
                          const float* __restrict__ b, float* __restrict__ y) {
    constexpr int TPB = 256;
    constexpr int E = W / TPB;
    int row = blockIdx.x;
    const float* xr = x + (size_t)row * W;
    float v[E];
    float s = 0.f, s2 = 0.f;
#pragma unroll
    for (int e = 0; e < E; e++) {
        v[e] = xr[threadIdx.x + e * TPB];
        s += v[e];
        s2 += v[e] * v[e];
    }
    __shared__ float sh1[8], sh2[8];
#pragma unroll
    for (int o = 16; o; o >>= 1) {
        s  += __shfl_xor_sync(0xFFFFFFFFu, s, o);
        s2 += __shfl_xor_sync(0xFFFFFFFFu, s2, o);
    }
    int w = threadIdx.x >> 5;
    if ((threadIdx.x & 31) == 0) { sh1[w] = s; sh2[w] = s2; }
    __syncthreads();
    if (threadIdx.x < 32) {
        s  = (threadIdx.x < 8) ? sh1[threadIdx.x] : 0.f;
        s2 = (threadIdx.x < 8) ? sh2[threadIdx.x] : 0.f;
#pragma unroll
        for (int o = 4; o; o >>= 1) {
            s  += __shfl_xor_sync(0xFFFFFFFFu, s, o);
            s2 += __shfl_xor_sync(0xFFFFFFFFu, s2, o);
        }
        if (threadIdx.x == 0) { sh1[0] = s; sh2[0] = s2; }
    }
    __syncthreads();
    const float inv = 1.0f / (float)W;
    float m   = sh1[0] * inv;
    float var = sh2[0] * inv - m * m;
    float rs  = rsqrtf(var + EPSc);
    float* yr = y + (size_t)row * W;
#pragma unroll
    for (int e = 0; e < E; e++) {
        int cidx = threadIdx.x + e * TPB;
        yr[cidx] = (v[e] - m) * rs * g[cidx] + b[cidx];
    }
}

// ---------------- TF32 tensor-core GEMM ----------------
// C[M,Nn] = A[M,K] @ W[Nn,K]^T (+bias) (+accumulate)
// BM=64, BN=128, BK=32, 256 threads (8 warps as 2x4), warp tile 32x32,
// mma.m16n8k8 tiles 2x4 per warp, double-buffered cp.async SMEM (48KB),
// XOR swizzle: addr(m,k) = m*32 + ((k>>2)^(m&7))*4 + (k&3)  [floats]
// Requires M%64==0, Nn%128==0, K%32==0 (12608/2304/768/2048 all satisfy).
template <bool ACCUM>
__global__ __launch_bounds__(256) void gemm_tf32(const float* __restrict__ A,
                                                 const float* __restrict__ W,
                                                 const float* __restrict__ bias,
                                                 float* __restrict__ C,
                                                 int M, int Nn, int K) {
    __shared__ float As[2][64 * 32];
    __shared__ float Ws[2][128 * 32];

    const int t    = threadIdx.x;
    const int lane = t & 31;
    const int wid  = t >> 5;
    const int wm   = wid >> 2;      // 0..1
    const int wn   = wid & 3;       // 0..3
    const int g    = lane >> 2;     // 0..7
    const int kq   = lane & 3;      // 0..3
    const int bm   = blockIdx.y * 64;
    const int bn   = blockIdx.x * 128;
    const int nt   = K >> 5;

    // per-thread load slots (precompute swizzled SMEM byte offsets)
    // A: 64 rows x 8 f4 = 512 f4 -> 2 per thread; W: 1024 f4 -> 4 per thread
    int arow[2], akv[2]; uint32_t asoff[2];
    int wrow[4], wkv[4]; uint32_t wsoff[4];
#pragma unroll
    for (int i = 0; i < 2; i++) {
        int f = t + i * 256;
        arow[i] = f >> 3; akv[i] = f & 7;
        asoff[i] = (uint32_t)((arow[i] * 8 + (akv[i] ^ (arow[i] & 7))) * 16);
    }
#pragma unroll
    for (int i = 0; i < 4; i++) {
        int f = t + i * 256;
        wrow[i] = f >> 3; wkv[i] = f & 7;
        wsoff[i] = (uint32_t)((wrow[i] * 8 + (wkv[i] ^ (wrow[i] & 7))) * 16);
    }
    uint32_t asbase[2] = { smem_u32(&As[0][0]), smem_u32(&As[1][0]) };
    uint32_t wsbase[2] = { smem_u32(&Ws[0][0]), smem_u32(&Ws[1][0]) };

    float acc[2][4][4];
#pragma unroll
    for (int i = 0; i < 2; i++)
#pragma unroll
        for (int j = 0; j < 4; j++)
#pragma unroll
            for (int c = 0; c < 4; c++) acc[i][j][c] = 0.f;

    // prologue: load tile 0 into stage 0
    {
        const float* Ag = A + (size_t)bm * K;
        const float* Wg = W + (size_t)bn * K;
#pragma unroll
        for (int i = 0; i < 2; i++)
            cp16(asbase[0] + asoff[i], Ag + (size_t)arow[i] * K + akv[i] * 4);
#pragma unroll
        for (int i = 0; i < 4; i++)
            cp16(wsbase[0] + wsoff[i], Wg + (size_t)wrow[i] * K + wkv[i] * 4);
        asm volatile("cp.async.commit_group;");
    }

    for (int it = 0; it < nt; ++it) {
        const int st = it & 1;
        if (it + 1 < nt) {
            const int k0 = (it + 1) * 32;
            const float* Ag = A + (size_t)bm * K + k0;
            const float* Wg = W + (size_t)bn * K + k0;
#pragma unroll
            for (int i = 0; i < 2; i++)
                cp16(asbase[st ^ 1] + asoff[i], Ag + (size_t)arow[i] * K + akv[i] * 4);
#pragma unroll
            for (int i = 0; i < 4; i++)
                cp16(wsbase[st ^ 1] + wsoff[i], Wg + (size_t)wrow[i] * K + wkv[i] * 4);
            asm volatile("cp.async.commit_group;");
            asm volatile("cp.async.wait_group 1;");
        } else {
            asm volatile("cp.async.wait_group 0;");
        }
        __syncthreads();

        const float* as = As[st];
        const float* ws = Ws[st];
#pragma unroll
        for (int ks = 0; ks < 4; ks++) {
            const int krow = ks * 2;       // k>>2 for k in [ks*8, ks*8+3]
            uint32_t a[2][4], b[4][2];
#pragma unroll
            for (int tm = 0; tm < 2; tm++) {
                int m0 = wm * 32 + tm * 16 + g;
                int m1 = m0 + 8;
                a[tm][0] = f2tf32(as[m0 * 32 + ((krow    ) ^ (m0 & 7)) * 4 + kq]);
                a[tm][1] = f2tf32(as[m1 * 32 + ((krow    ) ^ (m1 & 7)) * 4 + kq]);
                a[tm][2] = f2tf32(as[m0 * 32 + ((krow + 1) ^ (m0 & 7)) * 4 + kq]);
                a[tm][3] = f2tf32(as[m1 * 32 + ((krow + 1) ^ (m1 & 7)) * 4 + kq]);
            }
#pragma unroll
            for (int tn = 0; tn < 4; tn++) {
                int n0 = wn * 32 + tn * 8 + g;
                b[tn][0] = f2tf32(ws[n0 * 32 + ((krow    ) ^ (n0 & 7)) * 4 + kq]);
                b[tn][1] = f2tf32(ws[n0 * 32 + ((krow + 1) ^ (n0 & 7)) * 4 + kq]);
            }
#pragma unroll
            for (int tm = 0; tm < 2; tm++)
#pragma unroll
                for (int tn = 0; tn < 4; tn++)
                    mma_tf32(acc[tm][tn], a[tm], b[tn]);
        }
        __syncthreads();
    }

    // epilogue
#pragma unroll
    for (int tm = 0; tm < 2; tm++) {
        int r0 = bm + wm * 32 + tm * 16 + g;
#pragma unroll
        for (int tn = 0; tn < 4; tn++) {
            int c0 = bn + wn * 32 + tn * 8 + kq * 2;
            float b0 = bias ? bias[c0] : 0.f;
            float b1 = bias ? bias[c0 + 1] : 0.f;
            float* p0 = C + (size_t)r0 * Nn + c0;
            float* p1 = C + (size_t)(r0 + 8) * Nn + c0;
            if (ACCUM) {
                p0[0] += acc[tm][tn][0] + b0;
                p0[1] += acc[tm][tn][1] + b1;
                p1[0] += acc[tm][tn][2] + b0;
                p1[1] += acc[tm][tn][3] + b1;
            } else {
                p0[0] = acc[tm][tn][0] + b0;
                p0[1] = acc[tm][tn][1] + b1;
                p1[0] = acc[tm][tn][2] + b0;
                p1[1] = acc[tm][tn][3] + b1;
            }
        }
    }
}

// ---------------- attention: scores = SCALE * q @ k^T, batched over B*NH ----------------
__global__ __launch_bounds__(256) void attn_scores(const float* __restrict__ q,
                                                   const float* __restrict__ k,
                                                   float* __restrict__ s) {
    int bh = blockIdx.z;
    __shared__ float Qs[64][33];   // [kk][row]
    __shared__ float Ks[64][33];
    int t = threadIdx.x;
    int r = t >> 3;               // 0..31
    int c = (t & 7) * 8;          // 0..56
    const float* qb = q + (size_t)bh * Nc * HDc;
    const float* kb = k + (size_t)bh * Nc * HDc;
    int qi = blockIdx.y * 32 + r;
    int ki = blockIdx.x * 32 + r;
#pragma unroll
    for (int u = 0; u < 8; u++) {
        Qs[c + u][r] = (qi < Nc) ? qb[(size_t)qi * HDc + c + u] : 0.f;
        Ks[c + u][r] = (ki < Nc) ? kb[(size_t)ki * HDc + c + u] : 0.f;
    }
    __syncthreads();
    int tx = t & 15, ty = t >> 4;
    float acc00 = 0.f, acc01 = 0.f, acc10 = 0.f, acc11 = 0.f;
#pragma unroll 8
    for (int kk = 0; kk < 64; kk++) {
        float a0 = Qs[kk][ty * 2], a1 = Qs[kk][ty * 2 + 1];
        float b0 = Ks[kk][tx * 2], b1 = Ks[kk][tx * 2 + 1];
        acc00 += a0 * b0; acc01 += a0 * b1;
        acc10 += a1 * b0; acc11 += a1 * b1;
    }
    float accs[2][2] = {{acc00, acc01}, {acc10, acc11}};
#pragma unroll
    for (int ii = 0; ii < 2; ii++)
#pragma unroll
        for (int jj = 0; jj < 2; jj++) {
            int i = blockIdx.y * 32 + ty * 2 + ii;
            int j = blockIdx.x * 32 + tx * 2 + jj;
            if (i < Nc && j < Nc)
                s[((size_t)bh * Nc + i) * Nc + j] = accs[ii][jj] * SCALEc;
        }
}

// ---------------- softmax: one warp per row of length 197 ----------------
__global__ void softmax_kernel(float* __restrict__ s) {
    const int rows = Bc * NHc * Nc;
    int row = blockIdx.x * 4 + (threadIdx.x >> 5);
    if (row >= rows) return;
    int lane = threadIdx.x & 31;
    float* p = s + (size_t)row * Nc;
    float vals[7];
    float mx = -3.0e38f;
#pragma unroll
    for (int i = 0; i < 7; i++) {
        int j = lane + i * 32;
        vals[i] = (j < Nc) ? p[j] : -3.0e38f;
        mx = fmaxf(mx, vals[i]);
    }
#pragma unroll
    for (int o = 16; o; o >>= 1) mx = fmaxf(mx, __shfl_xor_sync(0xFFFFFFFFu, mx, o));
    float sum = 0.f;
#pragma unroll
    for (int i = 0; i < 7; i++) {
        int j = lane + i * 32;
        float e = (j < Nc) ? __expf(vals[i] - mx) : 0.f;
        vals[i] = e;
        sum += e;
    }
#pragma unroll
    for (int o = 16; o; o >>= 1) sum += __shfl_xor_sync(0xFFFFFFFFu, sum, o);
    float inv = 1.f / sum;
#pragma unroll
    for (int i = 0; i < 7; i++) {
        int j = lane + i * 32;
        if (j < Nc) p[j] = vals[i] * inv;
    }
}

// ---------------- attention: O = S @ V, output written to [BN, C] layout ----------------
__global__ __launch_bounds__(256) void attn_pv(const float* __restrict__ s,
                                               const float* __restrict__ v,
                                               float* __restrict__ o) {
    int bh = blockIdx.y;
    int b = bh / NHc, h = bh - b * NHc;
    __shared__ float Ss[32][33];   // [i][j]
    __shared__ float Vs[32][65];   // [j][d]
    int t = threadIdx.x;
    int tx = t & 15, ty = t >> 4;
    float acc[2][4] = {};
    for (int j0 = 0; j0 < Nc; j0 += 32) {
        int r = t >> 3;            // 0..31
        int c4 = (t & 7) * 4;
        int gi = blockIdx.x * 32 + r;
#pragma unroll
        for (int u = 0; u < 4; u++) {
            int gj = j0 + c4 + u;
            Ss[r][c4 + u] = (gi < Nc && gj < Nc)
                          ? s[((size_t)bh * Nc + gi) * Nc + gj] : 0.f;
        }
        int c8 = (t & 7) * 8;
        int gj = j0 + r;
#pragma unroll
        for (int u = 0; u < 8; u++)
            Vs[r][c8 + u] = (gj < Nc) ? v[((size_t)bh * Nc + gj) * HDc + c8 + u] : 0.f;
        __syncthreads();
#pragma unroll 8
        for (int kk = 0; kk < 32; kk++) {
            float a0 = Ss[ty * 2][kk], a1 = Ss[ty * 2 + 1][kk];
#pragma unroll
            for (int jj = 0; jj < 4; jj++) {
                float w = Vs[kk][tx * 4 + jj];
                acc[0][jj] += a0 * w;
                acc[1][jj] += a1 * w;
            }
        }
        __syncthreads();
    }
#pragma unroll
    for (int ii = 0; ii < 2; ii++) {
        int i = blockIdx.x * 32 + ty * 2 + ii;
        if (i < Nc) {
#pragma unroll
            for (int jj = 0; jj < 4; jj++)
                o[((size_t)(b * Nc + i)) * Cc + h * HDc + tx * 4 + jj] = acc[ii][jj];
        }
    }
}

// ---------------- host orchestration ----------------
extern "C" void kernel_launch(void* const* d_in, const int* in_sizes, int n_in,
                              void* d_out, int out_size) {
    const float* x    = (const float*)d_in[0];
    const float* rope = (const float*)d_in[1];
    const float* qkvw = (const float*)d_in[2];
    const float* qb   = (const float*)d_in[3];
    const float* vb   = (const float*)d_in[4];
    const float* pw   = (const float*)d_in[5];
    const float* pb   = (const float*)d_in[6];
    const float* n1g  = (const float*)d_in[7];
    const float* n1b  = (const float*)d_in[8];
    const float* n2g  = (const float*)d_in[9];
    const float* n2b  = (const float*)d_in[10];
    const float* w1g  = (const float*)d_in[11];
    const float* b1g  = (const float*)d_in[12];
    const float* w1x  = (const float*)d_in[13];
    const float* b1x  = (const float*)d_in[14];
    const float* nmg  = (const float*)d_in[15];
    const float* nmb  = (const float*)d_in[16];
    const float* w2   = (const float*)d_in[17];
    const float* b2   = (const float*)d_in[18];
    float* h = (float*)d_out;

    float *yb, *qkvb, *qbuf, *kbuf, *vbuf, *sb, *aob, *g1b, *g2b;
    cudaGetSymbolAddress((void**)&yb,   g_y);
    cudaGetSymbolAddress((void**)&qkvb, g_qkv);
    cudaGetSymbolAddress((void**)&qbuf, g_q);
    cudaGetSymbolAddress((void**)&kbuf, g_k);
    cudaGetSymbolAddress((void**)&vbuf, g_v);
    cudaGetSymbolAddress((void**)&sb,   g_s);
    cudaGetSymbolAddress((void**)&aob,  g_ao);
    cudaGetSymbolAddress((void**)&g1b,  g_g1);
    cudaGetSymbolAddress((void**)&g2b,  g_g2);

    const int nHC = BNc * Cc;
    copy_kernel<<<(nHC + 255) / 256, 256>>>(h, x, nHC);

    for (int l = 0; l < Lc; l++) {
        const float* qkvw_l = qkvw + (size_t)l * 3 * Cc * Cc;
        const float* qb_l   = qb   + (size_t)l * Cc;
        const float* vb_l   = vb   + (size_t)l * Cc;
        const float* pw_l   = pw   + (size_t)l * Cc * Cc;
        const float* pb_l   = pb   + (size_t)l * Cc;
        const float* n1g_l  = n1g  + (size_t)l * Cc;
        const float* n1b_l  = n1b  + (size_t)l * Cc;
        const float* n2g_l  = n2g  + (size_t)l * Cc;
        const float* n2b_l  = n2b  + (size_t)l * Cc;
        const float* w1g_l  = w1g  + (size_t)l * HFc * Cc;
        const float* b1g_l  = b1g  + (size_t)l * HFc;
        const float* w1x_l  = w1x  + (size_t)l * HFc * Cc;
        const float* b1x_l  = b1x  + (size_t)l * HFc;
        const float* nmg_l  = nmg  + (size_t)l * HFc;
        const float* nmb_l  = nmb  + (size_t)l * HFc;
        const float* w2_l   = w2   + (size_t)l * Cc * HFc;
        const float* b2_l   = b2   + (size_t)l * Cc;

        // --- attention ---
        ln_kernel<Cc><<<BNc, 256>>>(h, n1g_l, n1b_l, yb);
        gemm_tf32<false><<<dim3(3 * Cc / 128, BNc / 64), 256>>>(
            yb, qkvw_l, nullptr, qkvb, BNc, 3 * Cc, Cc);
        {
            int n = Bc * NHc * Nc * (HDc / 2);
            qkv_rope_kernel<<<(n + 255) / 256, 256>>>(qkvb, qb_l, vb_l, rope,
                                                      qbuf, kbuf, vbuf);
        }
        attn_scores<<<dim3((Nc + 31) / 32, (Nc + 31) / 32, Bc * NHc), 256>>>(qbuf, kbuf, sb);
        {
            int rows = Bc * NHc * Nc;
            softmax_kernel<<<(rows + 3) / 4, 128>>>(sb);
        }
        attn_pv<<<dim3((Nc + 31) / 32, Bc * NHc), 256>>>(sb, vbuf, aob);
        gemm_tf32<true><<<dim3(Cc / 128, BNc / 64), 256>>>(
            aob, pw_l, pb_l, h, BNc, Cc, Cc);

        // --- SwiGLU MLP with inner LN ---
        ln_kernel<Cc><<<BNc, 256>>>(h, n2g_l, n2b_l, yb);
        gemm_tf32<false><<<dim3(HFc / 128, BNc / 64), 256>>>(
            yb, w1g_l, b1g_l, g1b, BNc, HFc, Cc);
        gemm_tf32<false><<<dim3(HFc / 128, BNc / 64), 256>>>(
            yb, w1x_l, b1x_l, g2b, BNc, HFc, Cc);
        {
            int n = BNc * HFc;
            silu_mul_kernel<<<(n + 255) / 256, 256>>>(g1b, g2b, n);
        }
        ln_kernel<HFc><<<BNc, 256>>>(g1b, nmg_l, nmb_l, g1b);
        gemm_tf32<true><<<dim3(Cc / 128, BNc / 64), 256>>>(
            g1b, w2_l, b2_l, h, BNc, Cc, HFc);
    }
}

// round 7
// speedup vs baseline: 4.7095x; 1.4054x over previous
#include <cuda_runtime.h>
#include <math.h>
#include <stdint.h>

// ---------------- problem constants ----------------
#define Lc   4
#define Bc   64
#define Nc   197
#define Cc   768
#define NHc  12
#define HDc  64
#define HFc  2048
#define BNc  (Bc*Nc)          // 12608 = 197*64
#define SCALEc 0.125f         // 64^-0.5
#define EPSc   1e-6f
#define SST  224              // padded score-row stride (7 * 32)

// ---------------- scratch (static device globals; no allocation) ----------------
// Slack regions stay zero forever (zero-initialized, never written) -> guard-free loads.
__device__ float g_y  [BNc*Cc];                    // LN output (tf32-rounded)
__device__ float g_qkv[BNc*3*Cc];                  // fused qkv GEMM output
__device__ float g_q  [BNc*Cc + 64*HDc];           // [B,NH,N,HD] + slack (B*NH*N rows of HD)
__device__ float g_k  [BNc*Cc + 64*HDc];
__device__ float g_v  [BNc*Cc + 64*HDc];
__device__ float g_s  [(Bc*NHc*Nc + 64) * SST];    // scores, stride SST, + slack rows
__device__ float g_ao [BNc*Cc];                    // attention out [BN,C] (tf32-rounded)
__device__ float g_g1 [BNc*HFc];                   // gate -> silu*x -> LN (in place)
__device__ float g_g2 [BNc*HFc];                   // value branch
__device__ float g_wr [28311552];                  // tf32-rounded weights (all layers)

// g_wr layout offsets (floats)
#define OFF_QKV 0
#define OFF_PW  7077888
#define OFF_W1G 9437184
#define OFF_W1X 15728640
#define OFF_W2  22020096

// ---------------- small device helpers ----------------
__device__ __forceinline__ uint32_t smem_u32(const void* p) {
    return (uint32_t)__cvta_generic_to_shared(p);
}
__device__ __forceinline__ uint32_t f2tf32(float x) {
    uint32_t r;
    asm("cvt.rna.tf32.f32 %0, %1;" : "=r"(r) : "f"(x));
    return r;
}
__device__ __forceinline__ void mma_tf32(float* c, const uint32_t* a, const uint32_t* b) {
    asm volatile(
        "mma.sync.aligned.m16n8k8.row.col.f32.tf32.tf32.f32 "
        "{%0,%1,%2,%3},{%4,%5,%6,%7},{%8,%9},{%0,%1,%2,%3};"
        : "+f"(c[0]), "+f"(c[1]), "+f"(c[2]), "+f"(c[3])
        : "r"(a[0]), "r"(a[1]), "r"(a[2]), "r"(a[3]), "r"(b[0]), "r"(b[1]));
}
__device__ __forceinline__ void cp16(uint32_t saddr, const void* gaddr) {
    asm volatile("cp.async.cg.shared.global [%0], [%1], 16;" :: "r"(saddr), "l"(gaddr));
}

// ---------------- elementwise helpers ----------------
__global__ void copy_kernel(float* __restrict__ dst, const float* __restrict__ src, int n) {
    int i = blockIdx.x * blockDim.x + threadIdx.x;
    if (i < n) dst[i] = src[i];
}

__global__ void round_tf32_kernel(float* __restrict__ dst, const float* __restrict__ src, int n) {
    int i = blockIdx.x * blockDim.x + threadIdx.x;
    if (i < n) dst[i] = __uint_as_float(f2tf32(src[i]));
}

// in-place: gate[i] = silu(gate[i]) * xv[i]
__global__ void silu_mul_kernel(float* __restrict__ gate,
                                const float* __restrict__ xv, int n) {
    int i = blockIdx.x * blockDim.x + threadIdx.x;
    if (i < n) {
        float z = gate[i];
        float sg = z / (1.f + __expf(-z));
        gate[i] = sg * xv[i];
    }
}

// fused: qkv [BN,3C] -> q/k/v [B,NH,N,HD] with biases, interleaved RoPE, SCALE folded into q
__global__ void qkv_rope_kernel(const float* __restrict__ qkv,
                                const float* __restrict__ qb,
                                const float* __restrict__ vb,
                                const float* __restrict__ rope,
                                float* __restrict__ q, float* __restrict__ k,
                                float* __restrict__ v) {
    const int total = Bc * NHc * Nc * (HDc / 2);
    int idx = blockIdx.x * blockDim.x + threadIdx.x;
    if (idx >= total) return;
    int p   = idx & 31;                  // pair 0..31
    int tkn = (idx >> 5) % Nc;
    int bh  = idx / (32 * Nc);
    int b = bh / NHc, hh = bh - b * NHc;
    int d0 = p * 2;
    int cidx = hh * HDc + d0;

    const float* src = qkv + ((size_t)(b * Nc + tkn)) * (3 * Cc);
    float q0 = src[cidx]            + qb[cidx];
    float q1 = src[cidx + 1]        + qb[cidx + 1];
    float k0 = src[Cc + cidx];
    float k1 = src[Cc + cidx + 1];
    float v0 = src[2 * Cc + cidx]     + vb[cidx];
    float v1 = src[2 * Cc + cidx + 1] + vb[cidx + 1];

    if (tkn > 0) {
        const float* rr = rope + (size_t)(tkn - 1) * (2 * HDc);  // [sin(64)|cos(64)]
        float s0 = rr[d0], s1 = rr[d0 + 1];
        float c0 = rr[HDc + d0], c1 = rr[HDc + d0 + 1];
        float nq0 = q0 * c0 - q1 * s0;
        float nq1 = q1 * c1 + q0 * s1;
        float nk0 = k0 * c0 - k1 * s0;
        float nk1 = k1 * c1 + k0 * s1;
        q0 = nq0; q1 = nq1; k0 = nk0; k1 = nk1;
    }
    q0 *= SCALEc; q1 *= SCALEc;   // fold softmax scale into q
    size_t dst = ((size_t)bh * Nc + tkn) * HDc + d0;
    q[dst] = q0; q[dst + 1] = q1;
    k[dst] = k0; k[dst + 1] = k1;
    v[dst] = v0; v[dst + 1] = v1;
}

// ---------------- LayerNorm (tf32-rounded output; feeds GEMMs) ----------------
template <int W>
__global__ void ln_kernel(const float* __restrict__ x, const float* __restrict__ g,
                          const float* __restrict__ b, float* __restrict__ y) {
    constexpr int TPB = 256;
    constexpr int E = W / TPB;
    int row = blockIdx.x;
    const float* xr = x + (size_t)row * W;
    float v[E];
    float s = 0.f, s2 = 0.f;
#pragma unroll
    for (int e = 0; e < E; e++) {
        v[e] = xr[threadIdx.x + e * TPB];
        s += v[e];
        s2 += v[e] * v[e];
    }
    __shared__ float sh1[8], sh2[8];
#pragma unroll
    for (int o = 16; o; o >>= 1) {
        s  += __shfl_xor_sync(0xFFFFFFFFu, s, o);
        s2 += __shfl_xor_sync(0xFFFFFFFFu, s2, o);
    }
    int w = threadIdx.x >> 5;
    if ((threadIdx.x & 31) == 0) { sh1[w] = s; sh2[w] = s2; }
    __syncthreads();
    if (threadIdx.x < 32) {
        s  = (threadIdx.x < 8) ? sh1[threadIdx.x] : 0.f;
        s2 = (threadIdx.x < 8) ? sh2[threadIdx.x] : 0.f;
#pragma unroll
        for (int o = 4; o; o >>= 1) {
            s  += __shfl_xor_sync(0xFFFFFFFFu, s, o);
            s2 += __shfl_xor_sync(0xFFFFFFFFu, s2, o);
        }
        if (threadIdx.x == 0) { sh1[0] = s; sh2[0] = s2; }
    }
    __syncthreads();
    const float inv = 1.0f / (float)W;
    float m   = sh1[0] * inv;
    float var = sh2[0] * inv - m * m;
    float rs  = rsqrtf(var + EPSc);
    float* yr = y + (size_t)row * W;
#pragma unroll
    for (int e = 0; e < E; e++) {
        int cidx = threadIdx.x + e * TPB;
        yr[cidx] = __uint_as_float(f2tf32((v[e] - m) * rs * g[cidx] + b[cidx]));
    }
}

// ---------------- TF32 tensor-core GEMM (inputs pre-rounded to tf32; no inner cvt) -------------
// C[M,Nn] = A[M,K] @ W[Nn,K]^T (+bias) (+accumulate). BM=64,BN=128,BK=32, 256 thr.
template <bool ACCUM>
__global__ __launch_bounds__(256) void gemm_tf32(const float* __restrict__ A,
                                                 const float* __restrict__ W,
                                                 const float* __restrict__ bias,
                                                 float* __restrict__ C,
                                                 int M, int Nn, int K) {
    __shared__ float As[2][64 * 32];
    __shared__ float Ws[2][128 * 32];

    const int t    = threadIdx.x;
    const int lane = t & 31;
    const int wid  = t >> 5;
    const int wm   = wid >> 2;      // 0..1
    const int wn   = wid & 3;       // 0..3
    const int g    = lane >> 2;     // 0..7
    const int kq   = lane & 3;      // 0..3
    const int bm   = blockIdx.y * 64;
    const int bn   = blockIdx.x * 128;
    const int nt   = K >> 5;

    int arow[2], akv[2]; uint32_t asoff[2];
    int wrow[4], wkv[4]; uint32_t wsoff[4];
#pragma unroll
    for (int i = 0; i < 2; i++) {
        int f = t + i * 256;
        arow[i] = f >> 3; akv[i] = f & 7;
        asoff[i] = (uint32_t)((arow[i] * 8 + (akv[i] ^ (arow[i] & 7))) * 16);
    }
#pragma unroll
    for (int i = 0; i < 4; i++) {
        int f = t + i * 256;
        wrow[i] = f >> 3; wkv[i] = f & 7;
        wsoff[i] = (uint32_t)((wrow[i] * 8 + (wkv[i] ^ (wrow[i] & 7))) * 16);
    }
    uint32_t asbase[2] = { smem_u32(&As[0][0]), smem_u32(&As[1][0]) };
    uint32_t wsbase[2] = { smem_u32(&Ws[0][0]), smem_u32(&Ws[1][0]) };

    float acc[2][4][4];
#pragma unroll
    for (int i = 0; i < 2; i++)
#pragma unroll
        for (int j = 0; j < 4; j++)
#pragma unroll
            for (int c = 0; c < 4; c++) acc[i][j][c] = 0.f;

    {
        const float* Ag = A + (size_t)bm * K;
        const float* Wg = W + (size_t)bn * K;
#pragma unroll
        for (int i = 0; i < 2; i++)
            cp16(asbase[0] + asoff[i], Ag + (size_t)arow[i] * K + akv[i] * 4);
#pragma unroll
        for (int i = 0; i < 4; i++)
            cp16(wsbase[0] + wsoff[i], Wg + (size_t)wrow[i] * K + wkv[i] * 4);
        asm volatile("cp.async.commit_group;");
    }

    for (int it = 0; it < nt; ++it) {
        const int st = it & 1;
        if (it + 1 < nt) {
            const int k0 = (it + 1) * 32;
            const float* Ag = A + (size_t)bm * K + k0;
            const float* Wg = W + (size_t)bn * K + k0;
#pragma unroll
            for (int i = 0; i < 2; i++)
                cp16(asbase[st ^ 1] + asoff[i], Ag + (size_t)arow[i] * K + akv[i] * 4);
#pragma unroll
            for (int i = 0; i < 4; i++)
                cp16(wsbase[st ^ 1] + wsoff[i], Wg + (size_t)wrow[i] * K + wkv[i] * 4);
            asm volatile("cp.async.commit_group;");
            asm volatile("cp.async.wait_group 1;");
        } else {
            asm volatile("cp.async.wait_group 0;");
        }
        __syncthreads();

        const uint32_t* as = (const uint32_t*)As[st];
        const uint32_t* ws = (const uint32_t*)Ws[st];
#pragma unroll
        for (int ks = 0; ks < 4; ks++) {
            const int krow = ks * 2;
            uint32_t a[2][4], b[4][2];
#pragma unroll
            for (int tm = 0; tm < 2; tm++) {
                int m0 = wm * 32 + tm * 16 + g;
                int m1 = m0 + 8;
                a[tm][0] = as[m0 * 32 + ((krow    ) ^ (m0 & 7)) * 4 + kq];
                a[tm][1] = as[m1 * 32 + ((krow    ) ^ (m1 & 7)) * 4 + kq];
                a[tm][2] = as[m0 * 32 + ((krow + 1) ^ (m0 & 7)) * 4 + kq];
                a[tm][3] = as[m1 * 32 + ((krow + 1) ^ (m1 & 7)) * 4 + kq];
            }
#pragma unroll
            for (int tn = 0; tn < 4; tn++) {
                int n0 = wn * 32 + tn * 8 + g;
                b[tn][0] = ws[n0 * 32 + ((krow    ) ^ (n0 & 7)) * 4 + kq];
                b[tn][1] = ws[n0 * 32 + ((krow + 1) ^ (n0 & 7)) * 4 + kq];
            }
#pragma unroll
            for (int tm = 0; tm < 2; tm++)
#pragma unroll
                for (int tn = 0; tn < 4; tn++)
                    mma_tf32(acc[tm][tn], a[tm], b[tn]);
        }
        __syncthreads();
    }

#pragma unroll
    for (int tm = 0; tm < 2; tm++) {
        int r0 = bm + wm * 32 + tm * 16 + g;
#pragma unroll
        for (int tn = 0; tn < 4; tn++) {
            int c0 = bn + wn * 32 + tn * 8 + kq * 2;
            float b0 = bias ? bias[c0] : 0.f;
            float b1 = bias ? bias[c0 + 1] : 0.f;
            float* p0 = C + (size_t)r0 * Nn + c0;
            float* p1 = C + (size_t)(r0 + 8) * Nn + c0;
            if (ACCUM) {
                p0[0] += acc[tm][tn][0] + b0;
                p0[1] += acc[tm][tn][1] + b1;
                p1[0] += acc[tm][tn][2] + b0;
                p1[1] += acc[tm][tn][3] + b1;
            } else {
                p0[0] = acc[tm][tn][0] + b0;
                p0[1] = acc[tm][tn][1] + b1;
                p1[0] = acc[tm][tn][2] + b0;
                p1[1] = acc[tm][tn][3] + b1;
            }
        }
    }
}

// ---------------- attention scores via tf32 MMA: S = q @ k^T (scale pre-folded) -------------
// grid (4 ktiles, 4 qtiles, B*NH); BM=BN=64, K=64 (2 x BK=32). Loads guard-free (slack-padded).
__global__ __launch_bounds__(256) void attn_scores_mma(const float* __restrict__ q,
                                                       const float* __restrict__ k,
                                                       float* __restrict__ s) {
    __shared__ float As[2][64 * 32];
    __shared__ float Bs[2][64 * 32];
    const int t = threadIdx.x, lane = t & 31, wid = t >> 5;
    const int wm = wid >> 2, wn = wid & 3, g = lane >> 2, kq = lane & 3;
    const int bh = blockIdx.z;
    const int qt = blockIdx.y * 64, kt = blockIdx.x * 64;
    const float* Ag = q + (size_t)bh * (Nc * HDc) + (size_t)qt * HDc;
    const float* Bg = k + (size_t)bh * (Nc * HDc) + (size_t)kt * HDc;

    int arow[2], akv[2]; uint32_t soff[2];
#pragma unroll
    for (int i = 0; i < 2; i++) {
        int f = t + i * 256;
        arow[i] = f >> 3; akv[i] = f & 7;
        soff[i] = (uint32_t)((arow[i] * 8 + (akv[i] ^ (arow[i] & 7))) * 16);
    }
    uint32_t ab[2] = { smem_u32(&As[0][0]), smem_u32(&As[1][0]) };
    uint32_t bb[2] = { smem_u32(&Bs[0][0]), smem_u32(&Bs[1][0]) };

    float acc[2][2][4];
#pragma unroll
    for (int i = 0; i < 2; i++)
#pragma unroll
        for (int j = 0; j < 2; j++)
#pragma unroll
            for (int c = 0; c < 4; c++) acc[i][j][c] = 0.f;

#pragma unroll
    for (int i = 0; i < 2; i++) {
        cp16(ab[0] + soff[i], Ag + (size_t)arow[i] * HDc + akv[i] * 4);
        cp16(bb[0] + soff[i], Bg + (size_t)arow[i] * HDc + akv[i] * 4);
    }
    asm volatile("cp.async.commit_group;");

    for (int it = 0; it < 2; ++it) {
        const int st = it & 1;
        if (it == 0) {
#pragma unroll
            for (int i = 0; i < 2; i++) {
                cp16(ab[1] + soff[i], Ag + (size_t)arow[i] * HDc + 32 + akv[i] * 4);
                cp16(bb[1] + soff[i], Bg + (size_t)arow[i] * HDc + 32 + akv[i] * 4);
            }
            asm volatile("cp.async.commit_group;");
            asm volatile("cp.async.wait_group 1;");
        } else {
            asm volatile("cp.async.wait_group 0;");
        }
        __syncthreads();
        const float* as = As[st];
        const float* bs = Bs[st];
#pragma unroll
        for (int ks = 0; ks < 4; ks++) {
            const int krow = ks * 2;
            uint32_t a[2][4], b[2][2];
#pragma unroll
            for (int tm = 0; tm < 2; tm++) {
                int m0 = wm * 32 + tm * 16 + g, m1 = m0 + 8;
                a[tm][0] = f2tf32(as[m0 * 32 + ((krow    ) ^ (m0 & 7)) * 4 + kq]);
                a[tm][1] = f2tf32(as[m1 * 32 + ((krow    ) ^ (m1 & 7)) * 4 + kq]);
                a[tm][2] = f2tf32(as[m0 * 32 + ((krow + 1) ^ (m0 & 7)) * 4 + kq]);
                a[tm][3] = f2tf32(as[m1 * 32 + ((krow + 1) ^ (m1 & 7)) * 4 + kq]);
            }
#pragma unroll
            for (int tn = 0; tn < 2; tn++) {
                int n0 = wn * 16 + tn * 8 + g;
                b[tn][0] = f2tf32(bs[n0 * 32 + ((krow    ) ^ (n0 & 7)) * 4 + kq]);
                b[tn][1] = f2tf32(bs[n0 * 32 + ((krow + 1) ^ (n0 & 7)) * 4 + kq]);
            }
#pragma unroll
            for (int tm = 0; tm < 2; tm++)
#pragma unroll
                for (int tn = 0; tn < 2; tn++)
                    mma_tf32(acc[tm][tn], a[tm], b[tn]);
        }
        __syncthreads();
    }

#pragma unroll
    for (int tm = 0; tm < 2; tm++) {
        int r0 = qt + wm * 32 + tm * 16 + g;
#pragma unroll
        for (int tn = 0; tn < 2; tn++) {
            int c0 = kt + wn * 16 + tn * 8 + kq * 2;
#pragma unroll
            for (int rr = 0; rr < 2; rr++) {
                int r = r0 + rr * 8;
                if (r < Nc) {
                    float* sp = s + ((size_t)bh * Nc + r) * SST;
                    if (c0 < Nc)     sp[c0]     = acc[tm][tn][rr * 2];
                    if (c0 + 1 < Nc) sp[c0 + 1] = acc[tm][tn][rr * 2 + 1];
                }
            }
        }
    }
}

// ---------------- softmax: one warp per row (stride SST, cols < 197) ----------------
__global__ void softmax_kernel(float* __restrict__ s) {
    const int rows = Bc * NHc * Nc;
    int row = blockIdx.x * 4 + (threadIdx.x >> 5);
    if (row >= rows) return;
    int lane = threadIdx.x & 31;
    float* p = s + (size_t)row * SST;
    float vals[7];
    float mx = -3.0e38f;
#pragma unroll
    for (int i = 0; i < 7; i++) {
        int j = lane + i * 32;
        vals[i] = (j < Nc) ? p[j] : -3.0e38f;
        mx = fmaxf(mx, vals[i]);
    }
#pragma unroll
    for (int o = 16; o; o >>= 1) mx = fmaxf(mx, __shfl_xor_sync(0xFFFFFFFFu, mx, o));
    float sum = 0.f;
#pragma unroll
    for (int i = 0; i < 7; i++) {
        int j = lane + i * 32;
        float e = (j < Nc) ? __expf(vals[i] - mx) : 0.f;
        vals[i] = e;
        sum += e;
    }
#pragma unroll
    for (int o = 16; o; o >>= 1) sum += __shfl_xor_sync(0xFFFFFFFFu, sum, o);
    float inv = 1.f / sum;
#pragma unroll
    for (int i = 0; i < 7; i++) {
        int j = lane + i * 32;
        if (j < Nc) p[j] = vals[i] * inv;
    }
}

// ---------------- attention PV via tf32 MMA: O = P @ V -> [BN, C] (tf32-rounded) -------------
// grid (4 mtiles, B*NH); BM=64, BN=64(HD), K=224 (7 x BK=32; padded cols/rows are zeros).
__global__ __launch_bounds__(256) void attn_pv_mma(const float* __restrict__ s,
                                                   const float* __restrict__ v,
                                                   float* __restrict__ o) {
    __shared__ float As[2][64 * 32];
    __shared__ float Vs[2][32 * 72];
    const int t = threadIdx.x, lane = t & 31, wid = t >> 5;
    const int wm = wid >> 2, wn = wid & 3, g = lane >> 2, kq = lane & 3;
    const int bh = blockIdx.y;
    const int mt = blockIdx.x * 64;
    const int b = bh / NHc, hh = bh - b * NHc;
    const float* Ag = s + ((size_t)bh * Nc + mt) * SST;
    const float* Vg = v + (size_t)bh * (Nc * HDc);

    int arow[2], akv[2]; uint32_t aoff[2];
    int vrow[2], vcol[2]; uint32_t voff[2];
#pragma unroll
    for (int i = 0; i < 2; i++) {
        int f = t + i * 256;
        arow[i] = f >> 3; akv[i] = f & 7;
        aoff[i] = (uint32_t)((arow[i] * 8 + (akv[i] ^ (arow[i] & 7))) * 16);
        vrow[i] = f >> 4; vcol[i] = f & 15;
        voff[i] = (uint32_t)((vrow[i] * 72 + vcol[i] * 4) * 4);
    }
    uint32_t ab[2] = { smem_u32(&As[0][0]), smem_u32(&As[1][0]) };
    uint32_t vb[2] = { smem_u32(&Vs[0][0]), smem_u32(&Vs[1][0]) };

    float acc[2][2][4];
#pragma unroll
    for (int i = 0; i < 2; i++)
#pragma unroll
        for (int j = 0; j < 2; j++)
#pragma unroll
            for (int c = 0; c < 4; c++) acc[i][j][c] = 0.f;

#pragma unroll
    for (int i = 0; i < 2; i++) {
        cp16(ab[0] + aoff[i], Ag + (size_t)arow[i] * SST + akv[i] * 4);
        cp16(vb[0] + voff[i], Vg + (size_t)vrow[i] * HDc + vcol[i] * 4);
    }
    asm volatile("cp.async.commit_group;");

    for (int it = 0; it < 7; ++it) {
        const int st = it & 1;
        if (it + 1 < 7) {
            const int k0 = (it + 1) * 32;
#pragma unroll
            for (int i = 0; i < 2; i++) {
                cp16(ab[st ^ 1] + aoff[i], Ag + (size_t)arow[i] * SST + k0 + akv[i] * 4);
                cp16(vb[st ^ 1] + voff[i], Vg + (size_t)(k0 + vrow[i]) * HDc + vcol[i] * 4);
            }
            asm volatile("cp.async.commit_group;");
            asm volatile("cp.async.wait_group 1;");
        } else {
            asm volatile("cp.async.wait_group 0;");
        }
        __syncthreads();
        const float* as = As[st];
        const float* vs = Vs[st];
#pragma unroll
        for (int ks = 0; ks < 4; ks++) {
            const int krow = ks * 2;
            uint32_t a[2][4], bfr[2][2];
#pragma unroll
            for (int tm = 0; tm < 2; tm++) {
                int m0 = wm * 32 + tm * 16 + g, m1 = m0 + 8;
                a[tm][0] = f2tf32(as[m0 * 32 + ((krow    ) ^ (m0 & 7)) * 4 + kq]);
                a[tm][1] = f2tf32(as[m1 * 32 + ((krow    ) ^ (m1 & 7)) * 4 + kq]);
                a[tm][2] = f2tf32(as[m0 * 32 + ((krow + 1) ^ (m0 & 7)) * 4 + kq]);
                a[tm][3] = f2tf32(as[m1 * 32 + ((krow + 1) ^ (m1 & 7)) * 4 + kq]);
            }
#pragma unroll
            for (int tn = 0; tn < 2; tn++) {
                int n0 = wn * 16 + tn * 8 + g;
                bfr[tn][0] = f2tf32(vs[(ks * 8 + kq    ) * 72 + n0]);
                bfr[tn][1] = f2tf32(vs[(ks * 8 + kq + 4) * 72 + n0]);
            }
#pragma unroll
            for (int tm = 0; tm < 2; tm++)
#pragma unroll
                for (int tn = 0; tn < 2; tn++)
                    mma_tf32(acc[tm][tn], a[tm], bfr[tn]);
        }
        __syncthreads();
    }

#pragma unroll
    for (int tm = 0; tm < 2; tm++) {
        int i0 = mt + wm * 32 + tm * 16 + g;
#pragma unroll
        for (int tn = 0; tn < 2; tn++) {
            int d0 = wn * 16 + tn * 8 + kq * 2;
#pragma unroll
            for (int rr = 0; rr < 2; rr++) {
                int i = i0 + rr * 8;
                if (i < Nc) {
                    float* op = o + ((size_t)b * Nc + i) * Cc + hh * HDc + d0;
                    op[0] = __uint_as_float(f2tf32(acc[tm][tn][rr * 2]));
                    op[1] = __uint_as_float(f2tf32(acc[tm][tn][rr * 2 + 1]));
                }
            }
        }
    }
}

// ---------------- host orchestration ----------------
extern "C" void kernel_launch(void* const* d_in, const int* in_sizes, int n_in,
                              void* d_out, int out_size) {
    const float* x    = (const float*)d_in[0];
    const float* rope = (const float*)d_in[1];
    const float* qkvw = (const float*)d_in[2];
    const float* qb   = (const float*)d_in[3];
    const float* vb   = (const float*)d_in[4];
    const float* pw   = (const float*)d_in[5];
    const float* pb   = (const float*)d_in[6];
    const float* n1g  = (const float*)d_in[7];
    const float* n1b  = (const float*)d_in[8];
    const float* n2g  = (const float*)d_in[9];
    const float* n2b  = (const float*)d_in[10];
    const float* w1g  = (const float*)d_in[11];
    const float* b1g  = (const float*)d_in[12];
    const float* w1x  = (const float*)d_in[13];
    const float* b1x  = (const float*)d_in[14];
    const float* nmg  = (const float*)d_in[15];
    const float* nmb  = (const float*)d_in[16];
    const float* w2   = (const float*)d_in[17];
    const float* b2   = (const float*)d_in[18];
    float* h = (float*)d_out;

    float *yb, *qkvb, *qbuf, *kbuf, *vbuf, *sb, *aob, *g1b, *g2b, *wr;
    cudaGetSymbolAddress((void**)&yb,   g_y);
    cudaGetSymbolAddress((void**)&qkvb, g_qkv);
    cudaGetSymbolAddress((void**)&qbuf, g_q);
    cudaGetSymbolAddress((void**)&kbuf, g_k);
    cudaGetSymbolAddress((void**)&vbuf, g_v);
    cudaGetSymbolAddress((void**)&sb,   g_s);
    cudaGetSymbolAddress((void**)&aob,  g_ao);
    cudaGetSymbolAddress((void**)&g1b,  g_g1);
    cudaGetSymbolAddress((void**)&g2b,  g_g2);
    cudaGetSymbolAddress((void**)&wr,   g_wr);

    const int nHC = BNc * Cc;
    copy_kernel<<<(nHC + 255) / 256, 256>>>(h, x, nHC);

    // pre-round all weights to tf32 (once per launch)
    {
        int n;
        n = Lc * 3 * Cc * Cc;  round_tf32_kernel<<<(n + 255) / 256, 256>>>(wr + OFF_QKV, qkvw, n);
        n = Lc * Cc * Cc;      round_tf32_kernel<<<(n + 255) / 256, 256>>>(wr + OFF_PW,  pw,   n);
        n = Lc * HFc * Cc;     round_tf32_kernel<<<(n + 255) / 256, 256>>>(wr + OFF_W1G, w1g,  n);
        n = Lc * HFc * Cc;     round_tf32_kernel<<<(n + 255) / 256, 256>>>(wr + OFF_W1X, w1x,  n);
        n = Lc * Cc * HFc;     round_tf32_kernel<<<(n + 255) / 256, 256>>>(wr + OFF_W2,  w2,   n);
    }

    for (int l = 0; l < Lc; l++) {
        const float* qkvw_l = wr + OFF_QKV + (size_t)l * 3 * Cc * Cc;
        const float* pw_l   = wr + OFF_PW  + (size_t)l * Cc * Cc;
        const float* w1g_l  = wr + OFF_W1G + (size_t)l * HFc * Cc;
        const float* w1x_l  = wr + OFF_W1X + (size_t)l * HFc * Cc;
        const float* w2_l   = wr + OFF_W2  + (size_t)l * Cc * HFc;
        const float* qb_l   = qb   + (size_t)l * Cc;
        const float* vb_l   = vb   + (size_t)l * Cc;
        const float* pb_l   = pb   + (size_t)l * Cc;
        const float* n1g_l  = n1g  + (size_t)l * Cc;
        const float* n1b_l  = n1b  + (size_t)l * Cc;
        const float* n2g_l  = n2g  + (size_t)l * Cc;
        const float* n2b_l  = n2b  + (size_t)l * Cc;
        const float* b1g_l  = b1g  + (size_t)l * HFc;
        const float* b1x_l  = b1x  + (size_t)l * HFc;
        const float* nmg_l  = nmg  + (size_t)l * HFc;
        const float* nmb_l  = nmb  + (size_t)l * HFc;
        const float* b2_l   = b2   + (size_t)l * Cc;

        // --- attention ---
        ln_kernel<Cc><<<BNc, 256>>>(h, n1g_l, n1b_l, yb);
        gemm_tf32<false><<<dim3(3 * Cc / 128, BNc / 64), 256>>>(
            yb, qkvw_l, nullptr, qkvb, BNc, 3 * Cc, Cc);
        {
            int n = Bc * NHc * Nc * (HDc / 2);
            qkv_rope_kernel<<<(n + 255) / 256, 256>>>(qkvb, qb_l, vb_l, rope,
                                                      qbuf, kbuf, vbuf);
        }
        attn_scores_mma<<<dim3(4, 4, Bc * NHc), 256>>>(qbuf, kbuf, sb);
        {
            int rows = Bc * NHc * Nc;
            softmax_kernel<<<(rows + 3) / 4, 128>>>(sb);
        }
        attn_pv_mma<<<dim3(4, Bc * NHc), 256>>>(sb, vbuf, aob);
        gemm_tf32<true><<<dim3(Cc / 128, BNc / 64), 256>>>(
            aob, pw_l, pb_l, h, BNc, Cc, Cc);

        // --- SwiGLU MLP with inner LN ---
        ln_kernel<Cc><<<BNc, 256>>>(h, n2g_l, n2b_l, yb);
        gemm_tf32<false><<<dim3(HFc / 128, BNc / 64), 256>>>(
            yb, w1g_l, b1g_l, g1b, BNc, HFc, Cc);
        gemm_tf32<false><<<dim3(HFc / 128, BNc / 64), 256>>>(
            yb, w1x_l, b1x_l, g2b, BNc, HFc, Cc);
        {
            int n = BNc * HFc;
            silu_mul_kernel<<<(n + 255) / 256, 256>>>(g1b, g2b, n);
        }
        ln_kernel<HFc><<<BNc, 256>>>(g1b, nmg_l, nmb_l, g1b);
        gemm_tf32<true><<<dim3(Cc / 128, BNc / 64), 256>>>(
            g1b, w2_l, b2_l, h, BNc, Cc, HFc);
    }
}